// round 5
// baseline (speedup 1.0000x reference)
#include <cuda_runtime.h>
#include <math.h>

#define NN 100000
#define EE 3200000

// ---------------- scratch (static __device__ globals: no allocs allowed) ----
__device__ float  g_h2[512];
__device__ float  g_deg[NN];
__device__ float  g_dinv[NN];
__device__ float2 g_ms1[NN];     // m1 * dinv  (gather side of conv1)
__device__ float2 g_agg1[NN];    // conv1 accumulator (init = self-loop term)
__device__ float  g_ms2[NN];     // m2 * dinv
__device__ float  g_agg2[NN];    // conv2 accumulator
__device__ int    g_src[EE];
__device__ int    g_dst[EE];
__device__ int    g_is64;

// ---------------- dtype detection: int64 vs int32 edge_index ---------------
// If buffer is int32, an int64 view of entry i is a + b*2^32 (b = next index,
// ~never 0 for 32 consecutive entries). If genuinely int64, all values < NN.
__global__ void k_detect(const long long* __restrict__ ei) {
    int ok = 1;
    for (int i = 0; i < 32; i++) {
        long long v = ei[i];
        if (v < 0 || v >= NN) { ok = 0; break; }
    }
    g_is64 = ok;
}

// ---------------- tiny MLP front: h2 = relu(relu(x@W1+b1)@W2+b2) -----------
// grid=4, block=256. Each block redundantly computes h1 (cheap, 128KB W1),
// then computes 128 h2 outputs with 2-way split-k for latency hiding.
__global__ void k_mlp_front(const float* __restrict__ x,
                            const float* __restrict__ W1,
                            const float* __restrict__ b1,
                            const float* __restrict__ W2,
                            const float* __restrict__ b2) {
    __shared__ float sx[128];
    __shared__ float sh1[256];
    __shared__ float red[256];
    int t = threadIdx.x;
    if (t < 128) sx[t] = x[t];
    __syncthreads();

    float acc = 0.f;
    #pragma unroll 8
    for (int k = 0; k < 128; k++) acc = fmaf(sx[k], W1[k * 256 + t], acc);
    sh1[t] = fmaxf(acc + b1[t], 0.f);
    __syncthreads();

    int j = blockIdx.x * 128 + (t & 127);
    int slice = t >> 7;              // 0 or 1
    float a2 = 0.f;
    int k0 = slice * 128;
    #pragma unroll 8
    for (int k = k0; k < k0 + 128; k++) a2 = fmaf(sh1[k], W2[k * 512 + j], a2);
    red[t] = a2;
    __syncthreads();
    if (slice == 0) {
        g_h2[j] = fmaxf(red[t] + red[t + 128] + b2[j], 0.f);
    }
}

// ---------------- degree init ----------------------------------------------
__global__ void k_deg_init() {
    int n = blockIdx.x * blockDim.x + threadIdx.x;
    if (n < NN) g_deg[n] = 1.0f;   // +1 self-loop
}

// ---------------- edge prep: unpack indices to int32 + degree scatter ------
__global__ void k_prep_edges(const void* __restrict__ ei, int E) {
    int e = blockIdx.x * blockDim.x + threadIdx.x;
    if (e >= E) return;
    int s, d;
    if (g_is64) {
        const long long* p = (const long long*)ei;
        s = (int)p[e];
        d = (int)p[E + e];
    } else {
        const int* p = (const int*)ei;
        s = p[e];
        d = p[E + e];
    }
    g_src[e] = s;
    g_dst[e] = d;
    atomicAdd(&g_deg[d], 1.0f);
}

// ---------------- dinv = deg^-1/2 ------------------------------------------
__global__ void k_dinv() {
    int n = blockIdx.x * blockDim.x + threadIdx.x;
    if (n < NN) g_dinv[n] = rsqrtf(g_deg[n]);
}

// ---------------- BIG GEMV: h = relu(h2 @ W3 + b3), fused conv1 prologue ---
// One thread per node n: float4 over the 4 features (cols 4n..4n+3).
// W3 row-major [512, 400000] -> float4 index k*100000 + n (coalesced).
__global__ void k_gemv(const float4* __restrict__ W3,
                       const float4* __restrict__ b3,
                       const float*  __restrict__ Wg1) {
    __shared__ float sh2[512];
    __shared__ float swg[8];
    int t = threadIdx.x;
    for (int i = t; i < 512; i += 256) sh2[i] = g_h2[i];
    if (t < 8) swg[t] = Wg1[t];
    __syncthreads();

    int n = blockIdx.x * 256 + t;
    if (n >= NN) return;

    float4 acc = b3[n];
    const float4* Wp = W3 + n;
    #pragma unroll 8
    for (int k = 0; k < 512; k++) {
        float4 w = Wp[k * 100000];
        float  h = sh2[k];
        acc.x = fmaf(h, w.x, acc.x);
        acc.y = fmaf(h, w.y, acc.y);
        acc.z = fmaf(h, w.z, acc.z);
        acc.w = fmaf(h, w.w, acc.w);
    }
    float h0 = fmaxf(acc.x, 0.f);
    float h1 = fmaxf(acc.y, 0.f);
    float h2 = fmaxf(acc.z, 0.f);
    float h3 = fmaxf(acc.w, 0.f);

    // m1 = h @ Wg1   (Wg1 row-major [4,2])
    float m0 = h0 * swg[0] + h1 * swg[2] + h2 * swg[4] + h3 * swg[6];
    float m1 = h0 * swg[1] + h1 * swg[3] + h2 * swg[5] + h3 * swg[7];

    float di = g_dinv[n];
    g_ms1[n]  = make_float2(m0 * di, m1 * di);
    g_agg1[n] = make_float2(m0 * di * di, m1 * di * di);   // self-loop: m/deg
}

// ---------------- conv1 edge scatter (vector RED, sm_90+) ------------------
__global__ void k_edge1(int E) {
    int e = blockIdx.x * blockDim.x + threadIdx.x;
    if (e >= E) return;
    int s = g_src[e], d = g_dst[e];
    float  nd = g_dinv[d];
    float2 ms = g_ms1[s];
    float2* p = &g_agg1[d];
    asm volatile("red.global.add.v2.f32 [%0], {%1, %2};"
                 :: "l"(p), "f"(ms.x * nd), "f"(ms.y * nd) : "memory");
}

// ---------------- conv1 epilogue + conv2 prologue --------------------------
__global__ void k_node2(const float* __restrict__ bg1,
                        const float* __restrict__ Wg2) {
    int n = blockIdx.x * blockDim.x + threadIdx.x;
    if (n >= NN) return;
    float2 a = g_agg1[n];
    float z0 = fmaxf(a.x + bg1[0], 0.f);
    float z1 = fmaxf(a.y + bg1[1], 0.f);
    float m2 = z0 * Wg2[0] + z1 * Wg2[1];
    float di = g_dinv[n];
    g_ms2[n]  = m2 * di;
    g_agg2[n] = m2 * di * di;     // self-loop term
}

// ---------------- conv2 edge scatter ---------------------------------------
__global__ void k_edge2(int E) {
    int e = blockIdx.x * blockDim.x + threadIdx.x;
    if (e >= E) return;
    int s = g_src[e], d = g_dst[e];
    atomicAdd(&g_agg2[d], g_ms2[s] * g_dinv[d]);
}

// ---------------- output: sigmoid ------------------------------------------
__global__ void k_out(float* __restrict__ out, const float* __restrict__ bg2) {
    int n = blockIdx.x * blockDim.x + threadIdx.x;
    if (n >= NN) return;
    float v = g_agg2[n] + bg2[0];
    out[n] = 1.0f / (1.0f + expf(-v));
}

// ---------------- launch ----------------------------------------------------
extern "C" void kernel_launch(void* const* d_in, const int* in_sizes, int n_in,
                              void* d_out, int out_size) {
    const float* x   = (const float*)d_in[0];
    const void*  ei  = d_in[1];
    const float* W1  = (const float*)d_in[2];
    const float* b1  = (const float*)d_in[3];
    const float* W2  = (const float*)d_in[4];
    const float* b2  = (const float*)d_in[5];
    const float* W3  = (const float*)d_in[6];
    const float* b3  = (const float*)d_in[7];
    const float* Wg1 = (const float*)d_in[8];
    const float* bg1 = (const float*)d_in[9];
    const float* Wg2 = (const float*)d_in[10];
    const float* bg2 = (const float*)d_in[11];
    float* out = (float*)d_out;

    int E = in_sizes[1] / 2;
    if (E > EE) E = EE;

    const int TB = 256;
    int gN = (NN + TB - 1) / TB;
    int gE = (E + TB - 1) / TB;

    k_detect<<<1, 1>>>((const long long*)ei);
    k_mlp_front<<<4, TB>>>(x, W1, b1, W2, b2);
    k_deg_init<<<gN, TB>>>();
    k_prep_edges<<<gE, TB>>>(ei, E);
    k_dinv<<<gN, TB>>>();
    k_gemv<<<gN, TB>>>((const float4*)W3, (const float4*)b3, Wg1);
    k_edge1<<<gE, TB>>>(E);
    k_node2<<<gN, TB>>>(bg1, Wg2);
    k_edge2<<<gE, TB>>>(E);
    k_out<<<gN, TB>>>(out, bg2);
}

// round 6
// speedup vs baseline: 1.0041x; 1.0041x over previous
#include <cuda_runtime.h>
#include <math.h>

#define NN 100000
#define EE 3200000

// ---------------- scratch (static __device__ globals: no allocs allowed) ----
__device__ float  g_h2[512];
__device__ float  g_deg[NN];
__device__ float  g_dinv[NN];
__device__ float2 g_ms1[NN];     // m1 * dinv  (gather side of conv1)
__device__ float2 g_agg1[NN];    // conv1 accumulator (init = self-loop term)
__device__ float  g_ms2[NN];     // m2 * dinv
__device__ float  g_agg2[NN];    // conv2 accumulator
__device__ int    g_src[EE];
__device__ int    g_dst[EE];
__device__ int    g_is64;

// ---------------- dtype detection: int64 vs int32 edge_index ---------------
// If buffer is int32, an int64 view of entry i is a + b*2^32 (b = next index,
// ~never 0 for 32 consecutive entries). If genuinely int64, all values < NN.
__global__ void k_detect(const long long* __restrict__ ei) {
    int ok = 1;
    for (int i = 0; i < 32; i++) {
        long long v = ei[i];
        if (v < 0 || v >= NN) { ok = 0; break; }
    }
    g_is64 = ok;
}

// ---------------- tiny MLP front: h2 = relu(relu(x@W1+b1)@W2+b2) -----------
// grid=4, block=256. Each block redundantly computes h1 (cheap, 128KB W1),
// then computes 128 h2 outputs with 2-way split-k for latency hiding.
__global__ void k_mlp_front(const float* __restrict__ x,
                            const float* __restrict__ W1,
                            const float* __restrict__ b1,
                            const float* __restrict__ W2,
                            const float* __restrict__ b2) {
    __shared__ float sx[128];
    __shared__ float sh1[256];
    __shared__ float red[256];
    int t = threadIdx.x;
    if (t < 128) sx[t] = x[t];
    __syncthreads();

    float acc = 0.f;
    #pragma unroll 8
    for (int k = 0; k < 128; k++) acc = fmaf(sx[k], W1[k * 256 + t], acc);
    sh1[t] = fmaxf(acc + b1[t], 0.f);
    __syncthreads();

    int j = blockIdx.x * 128 + (t & 127);
    int slice = t >> 7;              // 0 or 1
    float a2 = 0.f;
    int k0 = slice * 128;
    #pragma unroll 8
    for (int k = k0; k < k0 + 128; k++) a2 = fmaf(sh1[k], W2[k * 512 + j], a2);
    red[t] = a2;
    __syncthreads();
    if (slice == 0) {
        g_h2[j] = fmaxf(red[t] + red[t + 128] + b2[j], 0.f);
    }
}

// ---------------- degree init ----------------------------------------------
__global__ void k_deg_init() {
    int n = blockIdx.x * blockDim.x + threadIdx.x;
    if (n < NN) g_deg[n] = 1.0f;   // +1 self-loop
}

// ---------------- edge prep: unpack indices to int32 + degree scatter ------
__global__ void k_prep_edges(const void* __restrict__ ei, int E) {
    int e = blockIdx.x * blockDim.x + threadIdx.x;
    if (e >= E) return;
    int s, d;
    if (g_is64) {
        const long long* p = (const long long*)ei;
        s = (int)p[e];
        d = (int)p[E + e];
    } else {
        const int* p = (const int*)ei;
        s = p[e];
        d = p[E + e];
    }
    g_src[e] = s;
    g_dst[e] = d;
    atomicAdd(&g_deg[d], 1.0f);
}

// ---------------- dinv = deg^-1/2 ------------------------------------------
__global__ void k_dinv() {
    int n = blockIdx.x * blockDim.x + threadIdx.x;
    if (n < NN) g_dinv[n] = rsqrtf(g_deg[n]);
}

// ---------------- BIG GEMV: h = relu(h2 @ W3 + b3), fused conv1 prologue ---
// One thread per node n: float4 over the 4 features (cols 4n..4n+3).
// W3 row-major [512, 400000] -> float4 index k*100000 + n (coalesced).
__global__ void k_gemv(const float4* __restrict__ W3,
                       const float4* __restrict__ b3,
                       const float*  __restrict__ Wg1) {
    __shared__ float sh2[512];
    __shared__ float swg[8];
    int t = threadIdx.x;
    for (int i = t; i < 512; i += 256) sh2[i] = g_h2[i];
    if (t < 8) swg[t] = Wg1[t];
    __syncthreads();

    int n = blockIdx.x * 256 + t;
    if (n >= NN) return;

    float4 acc = b3[n];
    const float4* Wp = W3 + n;
    #pragma unroll 8
    for (int k = 0; k < 512; k++) {
        float4 w = Wp[k * 100000];
        float  h = sh2[k];
        acc.x = fmaf(h, w.x, acc.x);
        acc.y = fmaf(h, w.y, acc.y);
        acc.z = fmaf(h, w.z, acc.z);
        acc.w = fmaf(h, w.w, acc.w);
    }
    float h0 = fmaxf(acc.x, 0.f);
    float h1 = fmaxf(acc.y, 0.f);
    float h2 = fmaxf(acc.z, 0.f);
    float h3 = fmaxf(acc.w, 0.f);

    // m1 = h @ Wg1   (Wg1 row-major [4,2])
    float m0 = h0 * swg[0] + h1 * swg[2] + h2 * swg[4] + h3 * swg[6];
    float m1 = h0 * swg[1] + h1 * swg[3] + h2 * swg[5] + h3 * swg[7];

    float di = g_dinv[n];
    g_ms1[n]  = make_float2(m0 * di, m1 * di);
    g_agg1[n] = make_float2(m0 * di * di, m1 * di * di);   // self-loop: m/deg
}

// ---------------- conv1 edge scatter (vector RED, sm_90+) ------------------
__global__ void k_edge1(int E) {
    int e = blockIdx.x * blockDim.x + threadIdx.x;
    if (e >= E) return;
    int s = g_src[e], d = g_dst[e];
    float  nd = g_dinv[d];
    float2 ms = g_ms1[s];
    float2* p = &g_agg1[d];
    asm volatile("red.global.add.v2.f32 [%0], {%1, %2};"
                 :: "l"(p), "f"(ms.x * nd), "f"(ms.y * nd) : "memory");
}

// ---------------- conv1 epilogue + conv2 prologue --------------------------
__global__ void k_node2(const float* __restrict__ bg1,
                        const float* __restrict__ Wg2) {
    int n = blockIdx.x * blockDim.x + threadIdx.x;
    if (n >= NN) return;
    float2 a = g_agg1[n];
    float z0 = fmaxf(a.x + bg1[0], 0.f);
    float z1 = fmaxf(a.y + bg1[1], 0.f);
    float m2 = z0 * Wg2[0] + z1 * Wg2[1];
    float di = g_dinv[n];
    g_ms2[n]  = m2 * di;
    g_agg2[n] = m2 * di * di;     // self-loop term
}

// ---------------- conv2 edge scatter ---------------------------------------
__global__ void k_edge2(int E) {
    int e = blockIdx.x * blockDim.x + threadIdx.x;
    if (e >= E) return;
    int s = g_src[e], d = g_dst[e];
    atomicAdd(&g_agg2[d], g_ms2[s] * g_dinv[d]);
}

// ---------------- output: sigmoid ------------------------------------------
__global__ void k_out(float* __restrict__ out, const float* __restrict__ bg2) {
    int n = blockIdx.x * blockDim.x + threadIdx.x;
    if (n >= NN) return;
    float v = g_agg2[n] + bg2[0];
    out[n] = 1.0f / (1.0f + expf(-v));
}

// ---------------- launch ----------------------------------------------------
extern "C" void kernel_launch(void* const* d_in, const int* in_sizes, int n_in,
                              void* d_out, int out_size) {
    const float* x   = (const float*)d_in[0];
    const void*  ei  = d_in[1];
    const float* W1  = (const float*)d_in[2];
    const float* b1  = (const float*)d_in[3];
    const float* W2  = (const float*)d_in[4];
    const float* b2  = (const float*)d_in[5];
    const float* W3  = (const float*)d_in[6];
    const float* b3  = (const float*)d_in[7];
    const float* Wg1 = (const float*)d_in[8];
    const float* bg1 = (const float*)d_in[9];
    const float* Wg2 = (const float*)d_in[10];
    const float* bg2 = (const float*)d_in[11];
    float* out = (float*)d_out;

    int E = in_sizes[1] / 2;
    if (E > EE) E = EE;

    const int TB = 256;
    int gN = (NN + TB - 1) / TB;
    int gE = (E + TB - 1) / TB;

    k_detect<<<1, 1>>>((const long long*)ei);
    k_mlp_front<<<4, TB>>>(x, W1, b1, W2, b2);
    k_deg_init<<<gN, TB>>>();
    k_prep_edges<<<gE, TB>>>(ei, E);
    k_dinv<<<gN, TB>>>();
    k_gemv<<<gN, TB>>>((const float4*)W3, (const float4*)b3, Wg1);
    k_edge1<<<gE, TB>>>(E);
    k_node2<<<gN, TB>>>(bg1, Wg2);
    k_edge2<<<gE, TB>>>(E);
    k_out<<<gN, TB>>>(out, bg2);
}